// round 12
// baseline (speedup 1.0000x reference)
#include <cuda_runtime.h>

#define NB     64
#define NPER   2048
#define NTOT   131072          // NB*NPER
#define EE     1048576
#define KSEL   1639
#define PTOT   104896          // NB*KSEL
#define RANK_ASC 209715        // EE-1 - int(0.8*(EE-1))

// output layout (float32, concatenated in reference return order)
#define O1 6713344             // PTOT*64
#define O2 8810496             // O1 + 2*EE
#define O3 17199104            // O2 + EE*8
#define O4 17304000            // O3 + PTOT

#define CBUF 4096

__device__ int      g_perm[PTOT];
__device__ int      g_newidx[NTOT];
__device__ unsigned g_Su[EE];            // order-preserving uint key of S
__device__ unsigned g_h1[65536];         // zero at load; self-zeroed each run
__device__ unsigned g_psum[64];
__device__ unsigned g_cbuf[CBUF];
__device__ unsigned g_cnt;               // zero at load; reset by k_pick
__device__ unsigned g_binT;
__device__ unsigned g_rank2;
__device__ unsigned g_uth;

__device__ __forceinline__ unsigned f2u(float f) {
    unsigned u = __float_as_uint(f);
    return (u & 0x80000000u) ? ~u : (u | 0x80000000u);
}

// #1: per-graph bitonic sort of (score desc, idx asc); perm + new_idx.
// Fused: batch_out (independent of sort result: batch_out[p] = p/KSEL).
__global__ void k_topk(const float* __restrict__ score, float* __restrict__ out) {
    __shared__ unsigned long long keys[NPER];
    int b = blockIdx.x, t = threadIdx.x;
    for (int p = b * 1024 + t; p < PTOT; p += NB * 1024)
        out[O3 + p] = (float)(p / KSEL);
    for (int i = t; i < NPER; i += blockDim.x) {
        unsigned su = f2u(score[b * NPER + i]);
        keys[i] = (((unsigned long long)(~su)) << 32) | (unsigned)i;
    }
    __syncthreads();
    for (int k = 2; k <= NPER; k <<= 1) {
        for (int j = k >> 1; j > 0; j >>= 1) {
            for (int i = t; i < NPER; i += blockDim.x) {
                int ixj = i ^ j;
                if (ixj > i) {
                    unsigned long long a = keys[i], c = keys[ixj];
                    bool up = ((i & k) == 0);
                    if ((a > c) == up) { keys[i] = c; keys[ixj] = a; }
                }
            }
            __syncthreads();
        }
    }
    for (int i = t; i < NPER; i += blockDim.x) {
        int local = (int)(keys[i] & 0xFFFFFFFFull);
        int node  = b * NPER + local;
        if (i < KSEL) {
            int p = b * KSEL + i;
            g_perm[p] = node;
            g_newidx[node] = p;
        } else {
            g_newidx[node] = -1;
        }
    }
}

// #2: fused edge kernel (best measured variant, R6): 2 edges per 16-lane group,
// S=exp(||x[row]-x[col]||) exact fp32 + pass-1 histogram + remapped edge
// indices + masked attr copy.
__global__ void k_S(const int* __restrict__ ei, const float4* __restrict__ xv,
                    const float4* __restrict__ attr4, float* __restrict__ out) {
    unsigned gid = blockIdx.x * blockDim.x + threadIdx.x;   // EE*8 threads
    int lane = threadIdx.x & 15;
    unsigned p = gid >> 4;                                   // pair id
    unsigned e0 = 2 * p, e1 = 2 * p + 1;
    int r0 = ei[e0], c0 = ei[EE + e0];
    int r1 = ei[e1], c1 = ei[EE + e1];
    float4 a0 = __ldg(&xv[(size_t)r0 * 16 + lane]);
    float4 b0 = __ldg(&xv[(size_t)c0 * 16 + lane]);
    float4 a1 = __ldg(&xv[(size_t)r1 * 16 + lane]);
    float4 b1 = __ldg(&xv[(size_t)c1 * 16 + lane]);
    float dx, dy, dz, dw;
    dx = a0.x - b0.x; dy = a0.y - b0.y; dz = a0.z - b0.z; dw = a0.w - b0.w;
    float sq0 = dx * dx + dy * dy + dz * dz + dw * dw;
    dx = a1.x - b1.x; dy = a1.y - b1.y; dz = a1.z - b1.z; dw = a1.w - b1.w;
    float sq1 = dx * dx + dy * dy + dz * dz + dw * dw;
#pragma unroll
    for (int o = 8; o; o >>= 1) {
        sq0 += __shfl_xor_sync(0xFFFFFFFFu, sq0, o, 16);
        sq1 += __shfl_xor_sync(0xFFFFFFFFu, sq1, o, 16);
    }
    if (lane < 4) {
        // lanes 0,1 -> edge e0;  lanes 2,3 -> edge e1
        unsigned e = (lane < 2) ? e0 : e1;
        int r = (lane < 2) ? r0 : r1;
        int c = (lane < 2) ? c0 : c1;
        float sq = (lane < 2) ? sq0 : sq1;
        int nr = g_newidx[r], nc = g_newidx[c];
        bool valid = (nr >= 0) && (nc >= 0);
        if ((lane & 1) == 0) {
            float S = expf(sqrtf(sq));   // sq==0 -> S=1, matches _safe_norm forward
            unsigned u = f2u(S);
            g_Su[e] = u;
            atomicAdd(&g_h1[u >> 16], 1u);
            out[O1 + e]      = valid ? (float)nr : -1.0f;
        } else {
            out[O1 + EE + e] = valid ? (float)nc : -1.0f;
        }
        float4 av = valid ? attr4[e * 2 + (lane & 1)] : make_float4(0, 0, 0, 0);
        ((float4*)(out + O2))[e * 2 + (lane & 1)] = av;
    }
}

// #3: parallel partial sums of h1: 64 blocks x 256 threads, 4 bins (uint4) each.
__global__ void k_sum() {
    const uint4* hist4 = (const uint4*)g_h1;
    __shared__ unsigned sh[8];
    int t = threadIdx.x;
    uint4 v = hist4[blockIdx.x * 256 + t];
    unsigned s = v.x + v.y + v.z + v.w;
#pragma unroll
    for (int o = 16; o; o >>= 1) s += __shfl_xor_sync(0xFFFFFFFFu, s, o);
    if ((t & 31) == 0) sh[t >> 5] = s;
    __syncthreads();
    if (t < 8) {
        s = sh[t];
#pragma unroll
        for (int o = 4; o; o >>= 1) s += __shfl_xor_sync(0xFFu, s, o, 8);
        if (t == 0) g_psum[blockIdx.x] = s;
    }
}

// #4: one block: psums staged via SMEM, shuffle-scan of winning 1024-bin chunk.
__global__ void k_find() {
    __shared__ unsigned warpsum[32];
    __shared__ unsigned spsum[64];
    __shared__ unsigned s_excl;
    __shared__ int s_blk;
    int t = threadIdx.x;
    const unsigned target = RANK_ASC;
    if (t < 64) spsum[t] = g_psum[t];
    __syncthreads();
    if (t == 0) {
        unsigned cum = 0;
        int B = 0;
        for (int i = 0; i < 64; i++) {
            unsigned p = spsum[i];
            if (target < cum + p) { B = i; break; }
            cum += p;
        }
        s_excl = cum; s_blk = B;
    }
    __syncthreads();
    int B = s_blk;
    unsigned h = g_h1[B * 1024 + t];
    unsigned inc = h;
#pragma unroll
    for (int o = 1; o < 32; o <<= 1) {
        unsigned n = __shfl_up_sync(0xFFFFFFFFu, inc, o);
        if ((t & 31) >= o) inc += n;
    }
    if ((t & 31) == 31) warpsum[t >> 5] = inc;
    __syncthreads();
    if (t < 32) {
        unsigned w = warpsum[t];
#pragma unroll
        for (int o = 1; o < 32; o <<= 1) {
            unsigned n = __shfl_up_sync(0xFFFFFFFFu, w, o);
            if (t >= o) w += n;
        }
        warpsum[t] = w;
    }
    __syncthreads();
    unsigned incl = inc + ((t >= 32) ? warpsum[(t >> 5) - 1] : 0u);
    unsigned excl = s_excl + incl - h;
    if (target >= excl && target < excl + h) {
        g_binT = (unsigned)(B * 1024 + t);
        g_rank2 = target - excl;
    }
}

// #5: collect the ~16 keys in the winning bin; self-zero h1 for next replay.
__global__ void k_collect() {
    int e = blockIdx.x * blockDim.x + threadIdx.x;
    if (blockIdx.x < 64)
        ((uint4*)g_h1)[blockIdx.x * 256 + threadIdx.x] = make_uint4(0, 0, 0, 0);
    unsigned u = g_Su[e];
    if ((u >> 16) == g_binT) {
        unsigned p = atomicAdd(&g_cnt, 1u);
        if (p < CBUF) g_cbuf[p] = u;
    }
}

// #6: one block: exact rank among the n collected keys -> g_uth (identical
// 32-bit threshold key as the old 2-pass histogram scheme). Resets g_cnt.
__global__ void k_pick() {
    __shared__ unsigned vals[CBUF];
    __shared__ unsigned s_n;
    int t = threadIdx.x;
    if (t == 0) s_n = min(g_cnt, (unsigned)CBUF);
    __syncthreads();
    unsigned n = s_n;
    for (unsigned i = t; i < n; i += 256) vals[i] = g_cbuf[i];
    __syncthreads();
    unsigned target = g_rank2;
    for (unsigned i = t; i < n; i += 256) {
        unsigned v = vals[i], less = 0, eq = 0;
        for (unsigned j = 0; j < n; j++) {
            less += (vals[j] < v);
            eq   += (vals[j] == v);
        }
        if (less <= target && target < less + eq) g_uth = v;
    }
    if (t == 0) g_cnt = 0;   // reset for next replay
}

// #7: select flags (EE) + x_out gather (16 threads/row, exact fp32).
__global__ void k_final(const float4* __restrict__ xv, float* __restrict__ out) {
    int t = blockIdx.x * blockDim.x + threadIdx.x;
    if (t < EE) out[O4 + t] = (g_Su[t] > g_uth) ? 1.0f : 0.0f;
    if (t < PTOT * 16) {
        int p = t >> 4, j = t & 15;
        int node = g_perm[p];
        ((float4*)out)[p * 16 + j] = xv[(size_t)node * 16 + j];
    }
}

extern "C" void kernel_launch(void* const* d_in, const int* in_sizes, int n_in,
                              void* d_out, int out_size) {
    const float* x    = (const float*)d_in[0];
    const float* xs   = (const float*)d_in[1];
    const int*   ei   = (const int*)d_in[2];
    const float* attr = (const float*)d_in[3];
    float* out = (float*)d_out;

    k_topk<<<NB, 1024>>>(xs, out);                                  // #1
    k_S<<<EE * 8 / 256, 256>>>(ei, (const float4*)x,
                               (const float4*)attr, out);           // #2
    k_sum<<<64, 256>>>();                                           // #3
    k_find<<<1, 1024>>>();                                          // #4
    k_collect<<<EE / 256, 256>>>();                                 // #5
    k_pick<<<1, 256>>>();                                           // #6
    k_final<<<PTOT * 16 / 256, 256>>>((const float4*)x, out);       // #7
}

// round 14
// speedup vs baseline: 1.6104x; 1.6104x over previous
#include <cuda_runtime.h>

#define NB     64
#define NPER   2048
#define NTOT   131072          // NB*NPER
#define EE     1048576
#define KSEL   1639
#define PTOT   104896          // NB*KSEL
#define RANK_ASC 209715        // EE-1 - int(0.8*(EE-1))

// output layout (float32, concatenated in reference return order)
#define O1 6713344             // PTOT*64
#define O2 8810496             // O1 + 2*EE
#define O3 17199104            // O2 + EE*8
#define O4 17304000            // O3 + PTOT

__device__ int      g_perm[PTOT];
__device__ int      g_newidx[NTOT];
__device__ unsigned g_Su[EE];            // order-preserving uint key of S
__device__ unsigned g_h1[65536];         // zero at load; self-zeroed by k_hist2
__device__ unsigned g_h2[65536];         // zero at load; self-zeroed by k_final
__device__ unsigned g_psum[64];
__device__ unsigned g_binT;
__device__ unsigned g_rank2;
__device__ unsigned g_uth;

__device__ __forceinline__ unsigned f2u(float f) {
    unsigned u = __float_as_uint(f);
    return (u & 0x80000000u) ? ~u : (u | 0x80000000u);
}

// #1: per-graph bitonic sort of (score desc, idx asc); perm + new_idx.
// Fused: batch_out (independent of sort result: batch_out[p] = p/KSEL).
__global__ void k_topk(const float* __restrict__ score, float* __restrict__ out) {
    __shared__ unsigned long long keys[NPER];
    int b = blockIdx.x, t = threadIdx.x;
    for (int p = b * 1024 + t; p < PTOT; p += NB * 1024)
        out[O3 + p] = (float)(p / KSEL);
    for (int i = t; i < NPER; i += blockDim.x) {
        unsigned su = f2u(score[b * NPER + i]);
        keys[i] = (((unsigned long long)(~su)) << 32) | (unsigned)i;
    }
    __syncthreads();
    for (int k = 2; k <= NPER; k <<= 1) {
        for (int j = k >> 1; j > 0; j >>= 1) {
            for (int i = t; i < NPER; i += blockDim.x) {
                int ixj = i ^ j;
                if (ixj > i) {
                    unsigned long long a = keys[i], c = keys[ixj];
                    bool up = ((i & k) == 0);
                    if ((a > c) == up) { keys[i] = c; keys[ixj] = a; }
                }
            }
            __syncthreads();
        }
    }
    for (int i = t; i < NPER; i += blockDim.x) {
        int local = (int)(keys[i] & 0xFFFFFFFFull);
        int node  = b * NPER + local;
        if (i < KSEL) {
            int p = b * KSEL + i;
            g_perm[p] = node;
            g_newidx[node] = p;
        } else {
            g_newidx[node] = -1;
        }
    }
}

// #2: fused edge kernel (best measured variant, R6): 2 edges per 16-lane group,
// S=exp(||x[row]-x[col]||) exact fp32 + pass-1 histogram + remapped edge
// indices + masked attr copy.
__global__ void k_S(const int* __restrict__ ei, const float4* __restrict__ xv,
                    const float4* __restrict__ attr4, float* __restrict__ out) {
    unsigned gid = blockIdx.x * blockDim.x + threadIdx.x;   // EE*8 threads
    int lane = threadIdx.x & 15;
    unsigned p = gid >> 4;                                   // pair id
    unsigned e0 = 2 * p, e1 = 2 * p + 1;
    int r0 = ei[e0], c0 = ei[EE + e0];
    int r1 = ei[e1], c1 = ei[EE + e1];
    float4 a0 = __ldg(&xv[(size_t)r0 * 16 + lane]);
    float4 b0 = __ldg(&xv[(size_t)c0 * 16 + lane]);
    float4 a1 = __ldg(&xv[(size_t)r1 * 16 + lane]);
    float4 b1 = __ldg(&xv[(size_t)c1 * 16 + lane]);
    float dx, dy, dz, dw;
    dx = a0.x - b0.x; dy = a0.y - b0.y; dz = a0.z - b0.z; dw = a0.w - b0.w;
    float sq0 = dx * dx + dy * dy + dz * dz + dw * dw;
    dx = a1.x - b1.x; dy = a1.y - b1.y; dz = a1.z - b1.z; dw = a1.w - b1.w;
    float sq1 = dx * dx + dy * dy + dz * dz + dw * dw;
#pragma unroll
    for (int o = 8; o; o >>= 1) {
        sq0 += __shfl_xor_sync(0xFFFFFFFFu, sq0, o, 16);
        sq1 += __shfl_xor_sync(0xFFFFFFFFu, sq1, o, 16);
    }
    if (lane < 4) {
        // lanes 0,1 -> edge e0;  lanes 2,3 -> edge e1
        unsigned e = (lane < 2) ? e0 : e1;
        int r = (lane < 2) ? r0 : r1;
        int c = (lane < 2) ? c0 : c1;
        float sq = (lane < 2) ? sq0 : sq1;
        int nr = g_newidx[r], nc = g_newidx[c];
        bool valid = (nr >= 0) && (nc >= 0);
        if ((lane & 1) == 0) {
            float S = expf(sqrtf(sq));   // sq==0 -> S=1, matches _safe_norm forward
            unsigned u = f2u(S);
            g_Su[e] = u;
            atomicAdd(&g_h1[u >> 16], 1u);
            out[O1 + e]      = valid ? (float)nr : -1.0f;
        } else {
            out[O1 + EE + e] = valid ? (float)nc : -1.0f;
        }
        float4 av = valid ? attr4[e * 2 + (lane & 1)] : make_float4(0, 0, 0, 0);
        ((float4*)(out + O2))[e * 2 + (lane & 1)] = av;
    }
}

// Parallel partial sums: 64 blocks x 256 threads, each thread 4 bins (uint4).
__global__ void k_sum(int pass) {
    const uint4* hist4 = (const uint4*)(pass ? g_h2 : g_h1);
    __shared__ unsigned sh[8];
    int t = threadIdx.x;
    uint4 v = hist4[blockIdx.x * 256 + t];
    unsigned s = v.x + v.y + v.z + v.w;
#pragma unroll
    for (int o = 16; o; o >>= 1) s += __shfl_xor_sync(0xFFFFFFFFu, s, o);
    if ((t & 31) == 0) sh[t >> 5] = s;
    __syncthreads();
    if (t < 8) {
        s = sh[t];
#pragma unroll
        for (int o = 4; o; o >>= 1) s += __shfl_xor_sync(0xFFu, s, o, 8);
        if (t == 0) g_psum[blockIdx.x] = s;
    }
}

// One block: psums staged via SMEM, then 1024 threads shuffle-scan the
// winning 1024-bin chunk.
__global__ void k_find(int pass) {
    __shared__ unsigned warpsum[32];
    __shared__ unsigned spsum[64];
    __shared__ unsigned s_excl;
    __shared__ int s_blk;
    const unsigned* hist = pass ? g_h2 : g_h1;
    int t = threadIdx.x;
    unsigned target = pass ? g_rank2 : (unsigned)RANK_ASC;
    if (t < 64) spsum[t] = g_psum[t];
    __syncthreads();
    if (t == 0) {
        unsigned cum = 0;
        int B = 0;
        for (int i = 0; i < 64; i++) {
            unsigned p = spsum[i];
            if (target < cum + p) { B = i; break; }
            cum += p;
        }
        s_excl = cum; s_blk = B;
    }
    __syncthreads();
    int B = s_blk;
    unsigned h = hist[B * 1024 + t];
    unsigned inc = h;
#pragma unroll
    for (int o = 1; o < 32; o <<= 1) {
        unsigned n = __shfl_up_sync(0xFFFFFFFFu, inc, o);
        if ((t & 31) >= o) inc += n;
    }
    if ((t & 31) == 31) warpsum[t >> 5] = inc;
    __syncthreads();
    if (t < 32) {
        unsigned w = warpsum[t];
#pragma unroll
        for (int o = 1; o < 32; o <<= 1) {
            unsigned n = __shfl_up_sync(0xFFFFFFFFu, w, o);
            if (t >= o) w += n;
        }
        warpsum[t] = w;
    }
    __syncthreads();
    unsigned incl = inc + ((t >= 32) ? warpsum[(t >> 5) - 1] : 0u);
    unsigned excl = s_excl + incl - h;
    if (target >= excl && target < excl + h) {
        unsigned bin = (unsigned)(B * 1024 + t);
        if (pass == 0) { g_binT = bin; g_rank2 = target - excl; }
        else           { g_uth = (g_binT << 16) | bin; }
    }
}

// Pass-2 histogram over low 16 bits of keys in the winning bin.
// Threads 0..16383 also re-zero g_h1 for the next replay (h1 is dead here).
__global__ void k_hist2() {
    int e = blockIdx.x * blockDim.x + threadIdx.x;
    if (e < 16384) ((uint4*)g_h1)[e] = make_uint4(0, 0, 0, 0);
    unsigned u = g_Su[e];
    if ((u >> 16) == g_binT) atomicAdd(&g_h2[u & 0xFFFFu], 1u);
}

// #final: select flags (EE) + x_out gather (16 threads/row, exact fp32).
// Threads 0..16383 also re-zero g_h2 for the next replay.
__global__ void k_final(const float4* __restrict__ xv, float* __restrict__ out) {
    int t = blockIdx.x * blockDim.x + threadIdx.x;
    if (t < 16384) ((uint4*)g_h2)[t] = make_uint4(0, 0, 0, 0);
    if (t < EE) out[O4 + t] = (g_Su[t] > g_uth) ? 1.0f : 0.0f;
    if (t < PTOT * 16) {
        int p = t >> 4, j = t & 15;
        int node = g_perm[p];
        ((float4*)out)[p * 16 + j] = xv[(size_t)node * 16 + j];
    }
}

extern "C" void kernel_launch(void* const* d_in, const int* in_sizes, int n_in,
                              void* d_out, int out_size) {
    const float* x    = (const float*)d_in[0];
    const float* xs   = (const float*)d_in[1];
    const int*   ei   = (const int*)d_in[2];
    const float* attr = (const float*)d_in[3];
    float* out = (float*)d_out;

    k_topk<<<NB, 1024>>>(xs, out);                                  // #1
    k_S<<<EE * 8 / 256, 256>>>(ei, (const float4*)x,
                               (const float4*)attr, out);           // #2
    k_sum<<<64, 256>>>(0);                                          // #3
    k_find<<<1, 1024>>>(0);                                         // #4
    k_hist2<<<EE / 256, 256>>>();                                   // #5
    k_sum<<<64, 256>>>(1);                                          // #6
    k_find<<<1, 1024>>>(1);                                         // #7
    k_final<<<PTOT * 16 / 256, 256>>>((const float4*)x, out);       // #8
}

// round 15
// speedup vs baseline: 1.6387x; 1.0176x over previous
#include <cuda_runtime.h>

#define NB     64
#define NPER   2048
#define NTOT   131072          // NB*NPER
#define EE     1048576
#define KSEL   1639
#define PTOT   104896          // NB*KSEL
#define RANK_ASC 209715        // EE-1 - int(0.8*(EE-1))

// output layout (float32, concatenated in reference return order)
#define O1 6713344             // PTOT*64
#define O2 8810496             // O1 + 2*EE
#define O3 17199104            // O2 + EE*8
#define O4 17304000            // O3 + PTOT

__device__ int      g_perm[PTOT];
__device__ int      g_newidx[NTOT];
__device__ unsigned g_Su[EE];            // order-preserving uint key of S
__device__ unsigned g_h1[65536];         // zero at load; self-zeroed by k_hist2
__device__ unsigned g_h2[65536];         // zero at load; self-zeroed by k_sel
__device__ unsigned g_psum[64];
__device__ unsigned g_binT;
__device__ unsigned g_rank2;
__device__ unsigned g_uth;

__device__ __forceinline__ unsigned f2u(float f) {
    unsigned u = __float_as_uint(f);
    return (u & 0x80000000u) ? ~u : (u | 0x80000000u);
}

// #1: per-graph bitonic sort of (score desc, idx asc); perm + new_idx.
__global__ void k_topk(const float* __restrict__ score) {
    __shared__ unsigned long long keys[NPER];
    int b = blockIdx.x, t = threadIdx.x;
    for (int i = t; i < NPER; i += blockDim.x) {
        unsigned su = f2u(score[b * NPER + i]);
        keys[i] = (((unsigned long long)(~su)) << 32) | (unsigned)i;
    }
    __syncthreads();
    for (int k = 2; k <= NPER; k <<= 1) {
        for (int j = k >> 1; j > 0; j >>= 1) {
            for (int i = t; i < NPER; i += blockDim.x) {
                int ixj = i ^ j;
                if (ixj > i) {
                    unsigned long long a = keys[i], c = keys[ixj];
                    bool up = ((i & k) == 0);
                    if ((a > c) == up) { keys[i] = c; keys[ixj] = a; }
                }
            }
            __syncthreads();
        }
    }
    for (int i = t; i < NPER; i += blockDim.x) {
        int local = (int)(keys[i] & 0xFFFFFFFFull);
        int node  = b * NPER + local;
        if (i < KSEL) {
            int p = b * KSEL + i;
            g_perm[p] = node;
            g_newidx[node] = p;
        } else {
            g_newidx[node] = -1;
        }
    }
}

// #2: fused edge kernel (R6 core): 2 edges per 16-lane group,
// S=exp(||x[row]-x[col]||) exact fp32 + pass-1 histogram + remapped edge
// indices + masked attr copy. NEW: epilogue does x_out gather + batch_out
// (select-independent, hides in the gather's idle DRAM/issue slots).
__global__ void k_S(const int* __restrict__ ei, const float4* __restrict__ xv,
                    const float4* __restrict__ attr4, float* __restrict__ out) {
    unsigned gid = blockIdx.x * blockDim.x + threadIdx.x;   // EE*8 threads
    int lane = threadIdx.x & 15;
    unsigned p = gid >> 4;                                   // pair id
    unsigned e0 = 2 * p, e1 = 2 * p + 1;
    int r0 = ei[e0], c0 = ei[EE + e0];
    int r1 = ei[e1], c1 = ei[EE + e1];
    float4 a0 = __ldg(&xv[(size_t)r0 * 16 + lane]);
    float4 b0 = __ldg(&xv[(size_t)c0 * 16 + lane]);
    float4 a1 = __ldg(&xv[(size_t)r1 * 16 + lane]);
    float4 b1 = __ldg(&xv[(size_t)c1 * 16 + lane]);
    float dx, dy, dz, dw;
    dx = a0.x - b0.x; dy = a0.y - b0.y; dz = a0.z - b0.z; dw = a0.w - b0.w;
    float sq0 = dx * dx + dy * dy + dz * dz + dw * dw;
    dx = a1.x - b1.x; dy = a1.y - b1.y; dz = a1.z - b1.z; dw = a1.w - b1.w;
    float sq1 = dx * dx + dy * dy + dz * dz + dw * dw;
#pragma unroll
    for (int o = 8; o; o >>= 1) {
        sq0 += __shfl_xor_sync(0xFFFFFFFFu, sq0, o, 16);
        sq1 += __shfl_xor_sync(0xFFFFFFFFu, sq1, o, 16);
    }
    if (lane < 4) {
        // lanes 0,1 -> edge e0;  lanes 2,3 -> edge e1
        unsigned e = (lane < 2) ? e0 : e1;
        int r = (lane < 2) ? r0 : r1;
        int c = (lane < 2) ? c0 : c1;
        float sq = (lane < 2) ? sq0 : sq1;
        int nr = g_newidx[r], nc = g_newidx[c];
        bool valid = (nr >= 0) && (nc >= 0);
        if ((lane & 1) == 0) {
            float S = expf(sqrtf(sq));   // sq==0 -> S=1, matches _safe_norm forward
            unsigned u = f2u(S);
            g_Su[e] = u;
            atomicAdd(&g_h1[u >> 16], 1u);
            out[O1 + e]      = valid ? (float)nr : -1.0f;
        } else {
            out[O1 + EE + e] = valid ? (float)nc : -1.0f;
        }
        float4 av = valid ? attr4[e * 2 + (lane & 1)] : make_float4(0, 0, 0, 0);
        ((float4*)(out + O2))[e * 2 + (lane & 1)] = av;
    }
    // epilogue: x_out gather (first PTOT*16 threads) + batch_out (first PTOT)
    if (gid < PTOT) out[O3 + gid] = (float)(gid / KSEL);
    if (gid < PTOT * 16) {
        int pp = gid >> 4, jj = gid & 15;
        int node = g_perm[pp];
        ((float4*)out)[pp * 16 + jj] = xv[(size_t)node * 16 + jj];
    }
}

// Parallel partial sums: 64 blocks x 256 threads, each thread 4 bins (uint4).
__global__ void k_sum(int pass) {
    const uint4* hist4 = (const uint4*)(pass ? g_h2 : g_h1);
    __shared__ unsigned sh[8];
    int t = threadIdx.x;
    uint4 v = hist4[blockIdx.x * 256 + t];
    unsigned s = v.x + v.y + v.z + v.w;
#pragma unroll
    for (int o = 16; o; o >>= 1) s += __shfl_xor_sync(0xFFFFFFFFu, s, o);
    if ((t & 31) == 0) sh[t >> 5] = s;
    __syncthreads();
    if (t < 8) {
        s = sh[t];
#pragma unroll
        for (int o = 4; o; o >>= 1) s += __shfl_xor_sync(0xFFu, s, o, 8);
        if (t == 0) g_psum[blockIdx.x] = s;
    }
}

// One block: psums staged via SMEM, then 1024 threads shuffle-scan the
// winning 1024-bin chunk.
__global__ void k_find(int pass) {
    __shared__ unsigned warpsum[32];
    __shared__ unsigned spsum[64];
    __shared__ unsigned s_excl;
    __shared__ int s_blk;
    const unsigned* hist = pass ? g_h2 : g_h1;
    int t = threadIdx.x;
    unsigned target = pass ? g_rank2 : (unsigned)RANK_ASC;
    if (t < 64) spsum[t] = g_psum[t];
    __syncthreads();
    if (t == 0) {
        unsigned cum = 0;
        int B = 0;
        for (int i = 0; i < 64; i++) {
            unsigned p = spsum[i];
            if (target < cum + p) { B = i; break; }
            cum += p;
        }
        s_excl = cum; s_blk = B;
    }
    __syncthreads();
    int B = s_blk;
    unsigned h = hist[B * 1024 + t];
    unsigned inc = h;
#pragma unroll
    for (int o = 1; o < 32; o <<= 1) {
        unsigned n = __shfl_up_sync(0xFFFFFFFFu, inc, o);
        if ((t & 31) >= o) inc += n;
    }
    if ((t & 31) == 31) warpsum[t >> 5] = inc;
    __syncthreads();
    if (t < 32) {
        unsigned w = warpsum[t];
#pragma unroll
        for (int o = 1; o < 32; o <<= 1) {
            unsigned n = __shfl_up_sync(0xFFFFFFFFu, w, o);
            if (t >= o) w += n;
        }
        warpsum[t] = w;
    }
    __syncthreads();
    unsigned incl = inc + ((t >= 32) ? warpsum[(t >> 5) - 1] : 0u);
    unsigned excl = s_excl + incl - h;
    if (target >= excl && target < excl + h) {
        unsigned bin = (unsigned)(B * 1024 + t);
        if (pass == 0) { g_binT = bin; g_rank2 = target - excl; }
        else           { g_uth = (g_binT << 16) | bin; }
    }
}

// Pass-2 histogram over low 16 bits of keys in the winning bin.
// Threads 0..16383 also re-zero g_h1 for the next replay (h1 is dead here).
__global__ void k_hist2() {
    int e = blockIdx.x * blockDim.x + threadIdx.x;
    if (e < 16384) ((uint4*)g_h1)[e] = make_uint4(0, 0, 0, 0);
    unsigned u = g_Su[e];
    if ((u >> 16) == g_binT) atomicAdd(&g_h2[u & 0xFFFFu], 1u);
}

// Select flags only; threads 0..16383 also re-zero g_h2 for the next replay.
__global__ void k_sel(float* __restrict__ out) {
    int t = blockIdx.x * blockDim.x + threadIdx.x;
    if (t < 16384) ((uint4*)g_h2)[t] = make_uint4(0, 0, 0, 0);
    out[O4 + t] = (g_Su[t] > g_uth) ? 1.0f : 0.0f;
}

extern "C" void kernel_launch(void* const* d_in, const int* in_sizes, int n_in,
                              void* d_out, int out_size) {
    const float* x    = (const float*)d_in[0];
    const float* xs   = (const float*)d_in[1];
    const int*   ei   = (const int*)d_in[2];
    const float* attr = (const float*)d_in[3];
    float* out = (float*)d_out;

    k_topk<<<NB, 1024>>>(xs);                                       // #1
    k_S<<<EE * 8 / 256, 256>>>(ei, (const float4*)x,
                               (const float4*)attr, out);           // #2
    k_sum<<<64, 256>>>(0);                                          // #3
    k_find<<<1, 1024>>>(0);                                         // #4
    k_hist2<<<EE / 256, 256>>>();                                   // #5
    k_sum<<<64, 256>>>(1);                                          // #6
    k_find<<<1, 1024>>>(1);                                         // #7
    k_sel<<<EE / 256, 256>>>(out);                                  // #8
}